// round 8
// baseline (speedup 1.0000x reference)
#include <cuda_runtime.h>

// LIF_ASC: T=4096 serial steps, B=256, N=12. Chain-bound ~92 cyc/step (R4).
// R8: latency HIDING, not shortening — each warp carries 4 batches
// (2 lane-groups x 2 temporal phases). Phases are independent; their
// STS->LDS->dot->pointwise chains overlap in one instruction stream.
// Per-phase math is R4 verbatim (same dot order -> same numerics).

#define TT 4096
#define BB 256
#define NN 12
#define CH 8

__device__ __forceinline__ float fmul_sat(float a, float b) {
    float r; asm("mul.rn.sat.f32 %0, %1, %2;" : "=f"(r) : "f"(a), "f"(b));
    return r;
}
__device__ __forceinline__ float ffma_sat(float a, float b, float c) {
    float r; asm("fma.rn.sat.f32 %0, %1, %2, %3;" : "=f"(r) : "f"(a), "f"(b), "f"(c));
    return r;
}

__global__ void __launch_bounds__(32, 1) lif_asc_kernel(
    const float* __restrict__ x_in,
    const float* __restrict__ w,
    const float* __restrict__ G,
    const float* __restrict__ E_L,
    const float* __restrict__ tau_m,
    const float* __restrict__ tau_s,
    const float* __restrict__ f_I,
    const int*   __restrict__ neuron_types,
    float* __restrict__ out)
{
    const int lane = threadIdx.x & 31;
    const int g    = lane >> 4;               // lane group (0/1)
    const int n    = lane & 15;               // neuron slot (active if < 12)
    const int nc   = (n < NN) ? n : (NN - 1);
    const bool active = (n < NN);

    // 4 batches per warp: phase p in {0,1}, group g in {0,1}.
    const int b0 = blockIdx.x * 4 + 0 * 2 + g;
    const int b1 = blockIdx.x * 4 + 1 * 2 + g;

    // Per-neuron params (runtime loads, exactly as R4).
    const float gG = G[nc];
    const float el = E_L[nc];
    const float tm = tau_m[nc];
    const float ts = tau_s[nc];
    const float fi = f_I[nc];

    const float thr     = 30.0f;
    const float norm_R  = (thr - el) * 1.1f;
    const float inv_tm  = 1.0f / tm;
    const float kA      = gG * el * inv_tm;
    const float kB      = gG * inv_tm;
    const float kV      = 1.0f - kB;
    const float kC      = norm_R * inv_tm;
    const float kC175   = kC * 1.75f;
    const float invthr  = 1.0f / thr;
    const float inv_dEL = 1.0f / (thr - el);
    const float ninv_dE = -inv_dEL;
    const float its     = 1.0f / ts;
    const float om_its  = 1.0f - its;
    const float om_f    = 1.0f - fi;
    const float BIG     = 1e30f;
    const float nThrBIG = -thr * BIG;

    // Weight column (0.5, sign, diag mask, kC folded) — same as R4.
    float wck[NN];
    #pragma unroll
    for (int j = 0; j < NN; j++) {
        float wj = 0.0f;
        if (active && j != n)
            wj = kC * 0.5f * w[j * NN + n] * (float)neuron_types[j];
        wck[j] = wj;
    }

    // Exchange: [parity][phase][g*16 + slot].
    __shared__ __align__(16) float buf[2][2][32];
    float* w00 = &buf[0][0][g * 16 + n];
    float* w10 = &buf[1][0][g * 16 + n];
    float* w01 = &buf[0][1][g * 16 + n];
    float* w11 = &buf[1][1][g * 16 + n];
    const float4* r00 = (const float4*)&buf[0][0][g * 16];
    const float4* r10 = (const float4*)&buf[1][0][g * 16];
    const float4* r01 = (const float4*)&buf[0][1][g * 16];
    const float4* r11 = (const float4*)&buf[1][1][g * 16];

    // Per-phase state.
    float v0 = 0.0f, s0 = 0.0f, Ia0 = 0.0f, a0 = 0.0f;
    float v1 = 0.0f, s1 = 0.0f, Ia1 = 0.0f, a1 = 0.0f;

    const int stride = BB * NN;
    const float* xp0 = x_in + b0 * NN + nc;
    const float* xp1 = x_in + b1 * NN + nc;
    float*       op0 = out  + b0 * NN + nc;
    float*       op1 = out  + b1 * NN + nc;

    float xb0[CH], xb1[CH];
    #pragma unroll
    for (int k = 0; k < CH; k++) { xb0[k] = xp0[k * stride]; xb1[k] = xp1[k * stride]; }

    // Body of one phase, given its freshly-loaded exchange vectors.
    #define BODY(A0_, A1_, A2_, xk_, v_, s_, Ia_, a_, opc_, k_)                  \
    {                                                                            \
        const float init  = fmaf(xk_, kC175, fmaf(v_, kV, kA));                  \
        const float voffn = v_ * ninv_dE;                                        \
        const float spre  = s_ * om_its;                                         \
        const float iam   = Ia_ * om_f;                                          \
        const float P     = spre + iam;                                          \
        float acc0 = fmaf(A0_.x, wck[0], init);                                  \
        float acc1 = A0_.y * wck[1];                                             \
        float acc2 = A0_.z * wck[2];                                             \
        float acc3 = A0_.w * wck[3];                                             \
        acc0 = fmaf(A1_.x, wck[4],  acc0);                                       \
        acc1 = fmaf(A1_.y, wck[5],  acc1);                                       \
        acc2 = fmaf(A1_.z, wck[6],  acc2);                                       \
        acc3 = fmaf(A1_.w, wck[7],  acc3);                                       \
        acc0 = fmaf(A2_.x, wck[8],  acc0);                                       \
        acc1 = fmaf(A2_.y, wck[9],  acc1);                                       \
        acc2 = fmaf(A2_.z, wck[10], acc2);                                       \
        acc3 = fmaf(A2_.w, wck[11], acc3);                                       \
        const float v_next = (acc0 + acc1) + (acc2 + acc3);                      \
        const float gating = fmul_sat(v_next, invthr);                           \
        const float dvclip = ffma_sat(v_next, inv_dEL, voffn);                   \
        const float spk01  = ffma_sat(v_next, BIG, nThrBIG);                     \
        const float m      = gating * dvclip;                                    \
        const float Pspk   = fmaf(spk01, fi, P);                                 \
        a_ = fmaf(m, its, Pspk);                                                 \
        const bool spiked = (v_next >= thr);                                     \
        v_  = spiked ? el : v_next;                                              \
        Ia_ = iam + (spiked ? fi : 0.0f);                                        \
        const float s2 = fmaf(m, its, spre);                                     \
        s_  = s2;                                                                \
        if (active) (opc_)[(k_) * stride] = s2 * ts;                             \
    }

    for (int tc = 0; tc < TT; tc += CH) {
        const int nb = min(tc + CH, TT - CH);
        const float* xn0p = xp0 + nb * stride;
        const float* xn1p = xp1 + nb * stride;
        float xn0[CH], xn1[CH];
        #pragma unroll
        for (int k = 0; k < CH; k++) { xn0[k] = xn0p[k * stride]; xn1[k] = xn1p[k * stride]; }

        float* oc0 = op0 + tc * stride;
        float* oc1 = op1 + tc * stride;

        #pragma unroll
        for (int k = 0; k < CH; k++) {
            // Both phases' stores first, then both loads, then both bodies:
            // phase-1 work fills phase-0's LDS window and vice versa.
            if (k & 1) { *w10 = a0; *w11 = a1; } else { *w00 = a0; *w01 = a1; }
            asm volatile("" ::: "memory");
            const float4* rp0 = (k & 1) ? r10 : r00;
            const float4* rp1 = (k & 1) ? r11 : r01;
            const float4 A00 = rp0[0], A01 = rp0[1], A02 = rp0[2];
            const float4 B00 = rp1[0], B01 = rp1[1], B02 = rp1[2];

            BODY(A00, A01, A02, xb0[k], v0, s0, Ia0, a0, oc0, k);
            BODY(B00, B01, B02, xb1[k], v1, s1, Ia1, a1, oc1, k);
        }

        #pragma unroll
        for (int k = 0; k < CH; k++) { xb0[k] = xn0[k]; xb1[k] = xn1[k]; }
    }
    #undef BODY
}

extern "C" void kernel_launch(void* const* d_in, const int* in_sizes, int n_in,
                              void* d_out, int out_size) {
    const float* x_in  = (const float*)d_in[0];
    const float* w     = (const float*)d_in[1];
    const float* G     = (const float*)d_in[2];
    const float* E_L   = (const float*)d_in[3];
    const float* tau_m = (const float*)d_in[4];
    const float* tau_s = (const float*)d_in[5];
    const float* f_I   = (const float*)d_in[6];
    const int*   nt    = (const int*)d_in[7];
    float* out = (float*)d_out;

    (void)in_sizes; (void)n_in; (void)out_size;

    // 64 blocks x 1 warp: 4 batches per warp (2 groups x 2 phases).
    lif_asc_kernel<<<BB / 4, 32>>>(x_in, w, G, E_L, tau_m, tau_s, f_I, nt, out);
}

// round 9
// speedup vs baseline: 1.2523x; 1.2523x over previous
#include <cuda_runtime.h>

// LIF_ASC: T=4096 serial steps, B=256, N=12. Chain ~73 cyc by DAG, 111 measured
// in R4 -> ~40 cyc MIO/scheduling slack. R9 = R4 with IDENTICAL arithmetic DAG,
// reordered memory traffic:
//  - one x-prefetch LDG per STEP, issued after the exchange LDS (R4 clustered
//    8 LDGs at chunk head, queueing the critical LDS behind them in the
//    in-order LSU; LDG->LDG floor 4 => ~32 cyc delay on step 0)
//  - single exchange buffer, no parity (STS->LDS adjacent, same-warp in-order;
//    next STS follows this LDS in program order -> no WAR hazard)

#define TT 4096
#define BB 256
#define NN 12
#define CH 8

__device__ __forceinline__ float fmul_sat(float a, float b) {
    float r; asm("mul.rn.sat.f32 %0, %1, %2;" : "=f"(r) : "f"(a), "f"(b));
    return r;
}
__device__ __forceinline__ float ffma_sat(float a, float b, float c) {
    float r; asm("fma.rn.sat.f32 %0, %1, %2, %3;" : "=f"(r) : "f"(a), "f"(b), "f"(c));
    return r;
}

__global__ void __launch_bounds__(32, 1) lif_asc_kernel(
    const float* __restrict__ x_in,
    const float* __restrict__ w,
    const float* __restrict__ G,
    const float* __restrict__ E_L,
    const float* __restrict__ tau_m,
    const float* __restrict__ tau_s,
    const float* __restrict__ f_I,
    const int*   __restrict__ neuron_types,
    float* __restrict__ out)
{
    const int lane = threadIdx.x & 31;
    const int g    = lane >> 4;               // batch group within warp (0/1)
    const int n    = lane & 15;               // neuron slot (active if < 12)
    const int nc   = (n < NN) ? n : (NN - 1);
    const int b    = blockIdx.x * 2 + g;
    const bool active = (n < NN);

    // Per-neuron params (runtime loads, exactly as R4 -> bit-identical numerics).
    const float gG = G[nc];
    const float el = E_L[nc];
    const float tm = tau_m[nc];
    const float ts = tau_s[nc];
    const float fi = f_I[nc];

    const float thr     = 30.0f;
    const float norm_R  = (thr - el) * 1.1f;
    const float inv_tm  = 1.0f / tm;
    const float kA      = gG * el * inv_tm;
    const float kB      = gG * inv_tm;
    const float kV      = 1.0f - kB;
    const float kC      = norm_R * inv_tm;
    const float kC175   = kC * 1.75f;
    const float invthr  = 1.0f / thr;
    const float inv_dEL = 1.0f / (thr - el);
    const float ninv_dE = -inv_dEL;
    const float its     = 1.0f / ts;
    const float om_its  = 1.0f - its;
    const float om_f    = 1.0f - fi;
    const float BIG     = 1e30f;
    const float nThrBIG = -thr * BIG;

    // Weight column (0.5, sign, diag mask, kC folded) — same as R4.
    float wck[NN];
    #pragma unroll
    for (int j = 0; j < NN; j++) {
        float wj = 0.0f;
        if (active && j != n)
            wj = kC * 0.5f * w[j * NN + n] * (float)neuron_types[j];
        wck[j] = wj;
    }

    // SINGLE exchange buffer: [group*16 + slot]. No parity needed: the LDS
    // directly follows the STS, and the next iteration's STS follows this
    // iteration's LDS in program order (same-warp LSU is in-order).
    __shared__ __align__(16) float buf[32];
    float* wq = &buf[g * 16 + n];
    const float4* rq = (const float4*)&buf[g * 16];

    float v = 0.0f, s = 0.0f, Ia = 0.0f, a = 0.0f;

    const int stride = BB * NN;
    const float* xp = x_in + b * NN + nc;     // clamped: always in-bounds
    float*       op = out  + b * NN + nc;

    // Prime first chunk.
    float xb[CH];
    #pragma unroll
    for (int k = 0; k < CH; k++)
        xb[k] = xp[k * stride];

    for (int tc = 0; tc < TT; tc += CH) {
        const int nb = min(tc + CH, TT - CH);  // clamped base: tail re-reads
        const float* xpn = xp + nb * stride;
        float* opc = op + tc * stride;
        float xn[CH];

        #pragma unroll
        for (int k = 0; k < CH; k++) {
            // ---- exchange a (critical): STS then immediate LDS ----
            *wq = a;
            asm volatile("" ::: "memory");
            const float4 A0 = rq[0];
            const float4 A1 = rq[1];
            const float4 A2 = rq[2];

            // ---- ONE prefetch LDG per step, behind the critical LDS ----
            xn[k] = xpn[k * stride];

            // ---- off-chain precomputes (entering state) in LDS shadow ----
            const float init  = fmaf(xb[k], kC175, fmaf(v, kV, kA));
            const float voffn = v * ninv_dE;
            const float spre  = s * om_its;
            const float iam   = Ia * om_f;
            const float P     = spre + iam;

            // ---- dot: EXACT R4 4-accumulator order ----
            float acc0 = fmaf(A0.x, wck[0], init);
            float acc1 = A0.y * wck[1];
            float acc2 = A0.z * wck[2];
            float acc3 = A0.w * wck[3];
            acc0 = fmaf(A1.x, wck[4],  acc0);
            acc1 = fmaf(A1.y, wck[5],  acc1);
            acc2 = fmaf(A1.z, wck[6],  acc2);
            acc3 = fmaf(A1.w, wck[7],  acc3);
            acc0 = fmaf(A2.x, wck[8],  acc0);
            acc1 = fmaf(A2.y, wck[9],  acc1);
            acc2 = fmaf(A2.z, wck[10], acc2);
            acc3 = fmaf(A2.w, wck[11], acc3);
            const float v_next = (acc0 + acc1) + (acc2 + acc3);

            // ---- chain pointwise: a(t+1) at v_next+12 ----
            const float gating = fmul_sat(v_next, invthr);
            const float dvclip = ffma_sat(v_next, inv_dEL, voffn);
            const float spk01  = ffma_sat(v_next, BIG, nThrBIG);
            const float m      = gating * dvclip;
            const float Pspk   = fmaf(spk01, fi, P);
            a = fmaf(m, its, Pspk);

            // ---- off-chain state (ALU pipe) + output ----
            const bool spiked = (v_next >= thr);
            v  = spiked ? el : v_next;
            Ia = iam + (spiked ? fi : 0.0f);
            const float s2 = fmaf(m, its, spre);
            s  = s2;
            if (active) opc[k * stride] = s2 * ts;
        }

        #pragma unroll
        for (int k = 0; k < CH; k++) xb[k] = xn[k];
    }
}

extern "C" void kernel_launch(void* const* d_in, const int* in_sizes, int n_in,
                              void* d_out, int out_size) {
    const float* x_in  = (const float*)d_in[0];
    const float* w     = (const float*)d_in[1];
    const float* G     = (const float*)d_in[2];
    const float* E_L   = (const float*)d_in[3];
    const float* tau_m = (const float*)d_in[4];
    const float* tau_s = (const float*)d_in[5];
    const float* f_I   = (const float*)d_in[6];
    const int*   nt    = (const int*)d_in[7];
    float* out = (float*)d_out;

    (void)in_sizes; (void)n_in; (void)out_size;

    // 128 blocks x 1 warp: one warp per SM, 2 batches per warp.
    lif_asc_kernel<<<BB / 2, 32>>>(x_in, w, G, E_L, tau_m, tau_s, f_I, nt, out);
}

// round 10
// speedup vs baseline: 1.2787x; 1.0211x over previous
#include <cuda_runtime.h>

// LIF_ASC: T=4096 serial steps, B=256, N=12. Latency-chain bound ~91.5ns/step.
// R10 = R9 with ONE change: the exchange's full compiler memory fence
// (asm volatile "" ::: "memory", once per step) is replaced by a single
// fused asm block: st.volatile.shared + 3x ld.volatile.shared.v4.
// Volatile shared ops are mutually ordered (STS->LDS preserved) but global
// LDG/STG and register scheduling are no longer fenced every step.
// Arithmetic DAG identical to R4/R9 -> rel_err must be bit-identical.

#define TT 4096
#define BB 256
#define NN 12
#define CH 8

__device__ __forceinline__ float fmul_sat(float a, float b) {
    float r; asm("mul.rn.sat.f32 %0, %1, %2;" : "=f"(r) : "f"(a), "f"(b));
    return r;
}
__device__ __forceinline__ float ffma_sat(float a, float b, float c) {
    float r; asm("fma.rn.sat.f32 %0, %1, %2, %3;" : "=f"(r) : "f"(a), "f"(b), "f"(c));
    return r;
}

// Fused exchange: write this lane's a, read the 12 group values.
// Ordered internally (volatile shared), NO global memory clobber.
__device__ __forceinline__ void exchange12(unsigned waddr, unsigned raddr,
                                           float a, float* o) {
    asm volatile(
        "st.volatile.shared.b32 [%12], %13;\n\t"
        "ld.volatile.shared.v4.f32 {%0,%1,%2,%3}, [%14];\n\t"
        "ld.volatile.shared.v4.f32 {%4,%5,%6,%7}, [%14+16];\n\t"
        "ld.volatile.shared.v4.f32 {%8,%9,%10,%11}, [%14+32];\n\t"
        : "=f"(o[0]), "=f"(o[1]), "=f"(o[2]),  "=f"(o[3]),
          "=f"(o[4]), "=f"(o[5]), "=f"(o[6]),  "=f"(o[7]),
          "=f"(o[8]), "=f"(o[9]), "=f"(o[10]), "=f"(o[11])
        : "r"(waddr), "f"(a), "r"(raddr));
}

__global__ void __launch_bounds__(32, 1) lif_asc_kernel(
    const float* __restrict__ x_in,
    const float* __restrict__ w,
    const float* __restrict__ G,
    const float* __restrict__ E_L,
    const float* __restrict__ tau_m,
    const float* __restrict__ tau_s,
    const float* __restrict__ f_I,
    const int*   __restrict__ neuron_types,
    float* __restrict__ out)
{
    const int lane = threadIdx.x & 31;
    const int g    = lane >> 4;               // batch group within warp (0/1)
    const int n    = lane & 15;               // neuron slot (active if < 12)
    const int nc   = (n < NN) ? n : (NN - 1);
    const int b    = blockIdx.x * 2 + g;
    const bool active = (n < NN);

    // Per-neuron params (runtime loads, exactly as R4 -> bit-identical numerics).
    const float gG = G[nc];
    const float el = E_L[nc];
    const float tm = tau_m[nc];
    const float ts = tau_s[nc];
    const float fi = f_I[nc];

    const float thr     = 30.0f;
    const float norm_R  = (thr - el) * 1.1f;
    const float inv_tm  = 1.0f / tm;
    const float kA      = gG * el * inv_tm;
    const float kB      = gG * inv_tm;
    const float kV      = 1.0f - kB;
    const float kC      = norm_R * inv_tm;
    const float kC175   = kC * 1.75f;
    const float invthr  = 1.0f / thr;
    const float inv_dEL = 1.0f / (thr - el);
    const float ninv_dE = -inv_dEL;
    const float its     = 1.0f / ts;
    const float om_its  = 1.0f - its;
    const float om_f    = 1.0f - fi;
    const float BIG     = 1e30f;
    const float nThrBIG = -thr * BIG;

    // Weight column (0.5, sign, diag mask, kC folded) — same as R4.
    float wck[NN];
    #pragma unroll
    for (int j = 0; j < NN; j++) {
        float wj = 0.0f;
        if (active && j != n)
            wj = kC * 0.5f * w[j * NN + n] * (float)neuron_types[j];
        wck[j] = wj;
    }

    // Single exchange buffer (no parity needed: ordered volatile shared ops;
    // next step's STS follows this step's LDS in the volatile chain).
    __shared__ __align__(16) float buf[32];
    const unsigned sbase = (unsigned)__cvta_generic_to_shared(buf);
    const unsigned waddr = sbase + 4u * (g * 16 + n);
    const unsigned raddr = sbase + 4u * (g * 16);

    float v = 0.0f, s = 0.0f, Ia = 0.0f, a = 0.0f;

    const int stride = BB * NN;
    const float* xp = x_in + b * NN + nc;     // clamped: always in-bounds
    float*       op = out  + b * NN + nc;

    // Prime first chunk.
    float xb[CH];
    #pragma unroll
    for (int k = 0; k < CH; k++)
        xb[k] = xp[k * stride];

    for (int tc = 0; tc < TT; tc += CH) {
        const int nb = min(tc + CH, TT - CH);  // clamped base: tail re-reads
        const float* xpn = xp + nb * stride;
        float* opc = op + tc * stride;
        float xn[CH];

        #pragma unroll
        for (int k = 0; k < CH; k++) {
            // ---- exchange a (critical): fused STS+3xLDS, no global fence ----
            float A[NN];
            exchange12(waddr, raddr, a, A);

            // ---- prefetch (free to move: no fence) ----
            xn[k] = xpn[k * stride];

            // ---- off-chain precomputes (entering state) in LDS shadow ----
            const float init  = fmaf(xb[k], kC175, fmaf(v, kV, kA));
            const float voffn = v * ninv_dE;
            const float spre  = s * om_its;
            const float iam   = Ia * om_f;
            const float P     = spre + iam;

            // ---- dot: EXACT R4 4-accumulator order ----
            float acc0 = fmaf(A[0], wck[0], init);
            float acc1 = A[1] * wck[1];
            float acc2 = A[2] * wck[2];
            float acc3 = A[3] * wck[3];
            acc0 = fmaf(A[4],  wck[4],  acc0);
            acc1 = fmaf(A[5],  wck[5],  acc1);
            acc2 = fmaf(A[6],  wck[6],  acc2);
            acc3 = fmaf(A[7],  wck[7],  acc3);
            acc0 = fmaf(A[8],  wck[8],  acc0);
            acc1 = fmaf(A[9],  wck[9],  acc1);
            acc2 = fmaf(A[10], wck[10], acc2);
            acc3 = fmaf(A[11], wck[11], acc3);
            const float v_next = (acc0 + acc1) + (acc2 + acc3);

            // ---- chain pointwise: a(t+1) at v_next+12 ----
            const float gating = fmul_sat(v_next, invthr);
            const float dvclip = ffma_sat(v_next, inv_dEL, voffn);
            const float spk01  = ffma_sat(v_next, BIG, nThrBIG);
            const float m      = gating * dvclip;
            const float Pspk   = fmaf(spk01, fi, P);
            a = fmaf(m, its, Pspk);

            // ---- off-chain state (ALU pipe) + output ----
            const bool spiked = (v_next >= thr);
            v  = spiked ? el : v_next;
            Ia = iam + (spiked ? fi : 0.0f);
            const float s2 = fmaf(m, its, spre);
            s  = s2;
            if (active) opc[k * stride] = s2 * ts;
        }

        #pragma unroll
        for (int k = 0; k < CH; k++) xb[k] = xn[k];
    }
}

extern "C" void kernel_launch(void* const* d_in, const int* in_sizes, int n_in,
                              void* d_out, int out_size) {
    const float* x_in  = (const float*)d_in[0];
    const float* w     = (const float*)d_in[1];
    const float* G     = (const float*)d_in[2];
    const float* E_L   = (const float*)d_in[3];
    const float* tau_m = (const float*)d_in[4];
    const float* tau_s = (const float*)d_in[5];
    const float* f_I   = (const float*)d_in[6];
    const int*   nt    = (const int*)d_in[7];
    float* out = (float*)d_out;

    (void)in_sizes; (void)n_in; (void)out_size;

    // 128 blocks x 1 warp: one warp per SM, 2 batches per warp.
    lif_asc_kernel<<<BB / 2, 32>>>(x_in, w, G, E_L, tau_m, tau_s, f_I, nt, out);
}